// round 12
// baseline (speedup 1.0000x reference)
#include <cuda_runtime.h>
#include <cstdint>

#define D_MODEL 1024
#define TPB     256            // 8 warps; warp w owns channels [w*128, w*128+128)
#define NWARP   (TPB / 32)
#define GRID    592            // 148 SMs x 4 CTAs: fully resident single wave
#define WF4     384            // per-warp W slice: 128 ch * 12 fl / 4 = 384 float4
#define PAD_F4  416            // padded per-warp SMEM region (stride-13 layout)
#define SMEM_BYTES (NWARP * PAD_F4 * 16)   // 53248 B

// ---------------------------------------------------------------------------
// Single fused kernel, fully WARP-INDEPENDENT (zero block-wide syncs).
//
// Linear(12->1024) over the polynomial feature map
//   feats = [t^2, t, t+1, t^2, 2t+2, -1, t^2, 0, 2t+1, t^2, 2t+1, 0]
// collapses per channel d to out[tok][d] = A[d]*t^2 + B[d]*t + C[d]:
//   A = w0+w3+w6+w9,  B = w1+w2+2*(w4+w8+w10),  C = w2+2*w4-w5+w8+w10 + b
//
// Each warp: (1) warp-local dtype ballot; (2) stages its own 6KB W slice
// with coalesced float4 loads into a padded SMEM region (write addr
// s = k + k/12; read addr lane*13+m -> 16B-unit stride 13 = conflict-free
// rotation); (3) holds its block's <=56 tokens in 2 registers/lane and
// broadcasts via __shfl in the stream loop. No __syncthreads anywhere:
// warps begin streaming the instant their own prologue finishes, removing
// the slowest-warp sync wall of the previous variant.
//
// Streaming: warp writes 512B contiguous per token (STG.128 x1/lane),
// balanced contiguous token partition across 592 blocks -> pinned at the
// ~6.1-6.4 TB/s store-path ceiling.
//
// dtype detection: probe first 16 odd 32-bit words; little-endian int64
// values < 32000 have all-zero high halves (P(false pos) ~ 32000^-16).
// ---------------------------------------------------------------------------
__global__ __launch_bounds__(TPB)
void n2_embed_warpind_kernel(const void* __restrict__ ntok_raw,
                             const float* __restrict__ W,
                             const float* __restrict__ b,
                             float4* __restrict__ out,
                             int n_tok) {
    extern __shared__ float4 sWall[];

    const int tid  = threadIdx.x;
    const int lane = tid & 31;
    const int w    = tid >> 5;
    const int bid  = blockIdx.x;
    const int*  pi  = (const int*)ntok_raw;
    const int2* pi2 = (const int2*)ntok_raw;

    // ---- warp-local dtype detection ----
    int probe = (lane < 16) ? pi[2 * lane + 1] : 0;
    unsigned any = __ballot_sync(0xFFFFFFFFu, probe != 0);
    const bool is64 = (any == 0);

    // ---- balanced contiguous token partition ----
    const int grid  = gridDim.x;
    const int q     = n_tok / grid;
    const int rem   = n_tok - q * grid;
    const int base  = q * bid + min(bid, rem);
    const int count = q + (bid < rem ? 1 : 0);   // <= 56

    // ---- tokens into registers (2 per lane cover count <= 64) ----
    float t0 = 0.0f, t1 = 0.0f;
    if (lane < count) {
        int idx = base + lane;
        t0 = is64 ? (float)pi2[idx].x : (float)pi[idx];
    }
    if (32 + lane < count) {
        int idx = base + 32 + lane;
        t1 = is64 ? (float)pi2[idx].x : (float)pi[idx];
    }

    // ---- stage this warp's 6KB W slice (coalesced) into padded SMEM ----
    const float4* Wg = (const float4*)W + w * WF4;
    float4* sw = sWall + w * PAD_F4;
#pragma unroll 4
    for (int r = 0; r < 12; r++) {
        int k = lane + 32 * r;                // consecutive across the warp
        float4 v = __ldg(Wg + k);
        sw[k + k / 12] = v;                   // padded: q -> q + q/12
    }
    __syncwarp();

    // ---- coefficients from SMEM (read addr = lane*13 + m) ----
    const float4* myW = sw + lane * 13;
    float A[4], B[4], C[4];
#pragma unroll
    for (int c4 = 0; c4 < 4; c4++) {
        float4 f0 = myW[3 * c4 + 0];          // w0 w1 w2 w3
        float4 f1 = myW[3 * c4 + 1];          // w4 w5 w6 w7
        float4 f2 = myW[3 * c4 + 2];          // w8 w9 w10 w11
        A[c4] = f0.x + f0.w + f1.z + f2.y;
        B[c4] = f0.y + f0.z + 2.0f * (f1.x + f2.x + f2.z);
        C[c4] = f0.z + 2.0f * f1.x - f1.y + f2.x + f2.z;
    }
    {
        // bias float4 for channels [w*128 + lane*4 ..+3] -> f4 index w*32+lane
        const float4 bias = __ldg((const float4*)b + (w * 32 + lane));
        C[0] += bias.x; C[1] += bias.y; C[2] += bias.z; C[3] += bias.w;
    }

    // ---- streaming loop: shfl token + 2 FMAs/channel + STG.128 ----
    const int row_f4 = D_MODEL / 4;           // 256 float4 per token row
    float4* outp = out + (size_t)base * row_f4 + (w * 32 + lane);

#pragma unroll 4
    for (int k = 0; k < count; k++) {
        float tsrc = (k < 32) ? t0 : t1;
        float t = __shfl_sync(0xFFFFFFFFu, tsrc, k & 31);
        float4 o;
        o.x = fmaf(fmaf(A[0], t, B[0]), t, C[0]);
        o.y = fmaf(fmaf(A[1], t, B[1]), t, C[1]);
        o.z = fmaf(fmaf(A[2], t, B[2]), t, C[2]);
        o.w = fmaf(fmaf(A[3], t, B[3]), t, C[3]);
        __stcs(outp, o);                      // evict-first: never re-read
        outp += row_f4;
    }
}

extern "C" void kernel_launch(void* const* d_in, const int* in_sizes, int n_in,
                              void* d_out, int out_size) {
    const void*  ntok = d_in[0];                 // int64 or int32 tokens [B*S]
    const float* W    = (const float*)d_in[1];   // [D_MODEL, 12] row-major
    const float* b    = (const float*)d_in[2];   // [D_MODEL]
    float4* out = (float4*)d_out;

    int n_tok = in_sizes[0];                     // 32768

    cudaFuncSetAttribute(n2_embed_warpind_kernel,
                         cudaFuncAttributeMaxDynamicSharedMemorySize,
                         SMEM_BYTES);
    n2_embed_warpind_kernel<<<GRID, TPB, SMEM_BYTES>>>(ntok, W, b, out, n_tok);
}

// round 13
// speedup vs baseline: 1.0417x; 1.0417x over previous
#include <cuda_runtime.h>
#include <cstdint>

#define D_MODEL 1024
#define TPB     256            // 8 warps; warp w owns channels [w*128, w*128+128)
#define NWARP   (TPB / 32)
#define GRID    592            // 148 SMs x 4 CTAs: fully resident single wave
#define MAXTOK  64             // ceil(32768/592) = 56
#define WF4     384            // per-warp W slice: 128 ch * 12 fl / 4 = 384 float4
#define PAD_F4  416            // padded per-warp region (stride-13 layout)
#define SMEM_BYTES (NWARP * PAD_F4 * 16)   // 53248 B dynamic (W)

// ---------------------------------------------------------------------------
// Single fused kernel, warp-independent prologue + LDS-broadcast stream loop.
//
// Linear(12->1024) over the polynomial feature map
//   feats = [t^2, t, t+1, t^2, 2t+2, -1, t^2, 0, 2t+1, t^2, 2t+1, 0]
// collapses per channel d to out[tok][d] = A[d]*t^2 + B[d]*t + C[d]:
//   A = w0+w3+w6+w9,  B = w1+w2+2*(w4+w8+w10),  C = w2+2*w4-w5+w8+w10 + b
//
// Design learned over R5..R12:
//  * Streaming floor = (134MB out + 7MB W) / ~6.4TB/s ~= 22us; everything
//    else is prologue/overhead engineering.
//  * Block-wide __syncthreads before streaming costs ~1.7us (slowest-warp
//    W wall, R11); per-iteration __shfl token broadcast costs ~0.8us (R12).
//  * This variant has NEITHER: each warp stages its own 6KB W slice AND its
//    own copy of the block's tokens into a warp-private SMEM strip
//    (__syncwarp only), then streams with a free LDS-broadcast token read.
//  * All global loads (12xW float4, 2x token, bias) are issued before any
//    STS so their latency overlaps setup math. Coalesced W loads keep the
//    L1tex wavefront count minimal; co-resident CTAs' identical W reads
//    merge in L1 MSHRs -> ~7MB L2-level W traffic.
//
// dtype detection: probe first 16 odd 32-bit words (warp-local ballot);
// little-endian int64 values < 32000 have all-zero high halves
// (P(false positive for int32) ~ 32000^-16).
// ---------------------------------------------------------------------------
__global__ __launch_bounds__(TPB)
void n2_embed_v13_kernel(const void* __restrict__ ntok_raw,
                         const float* __restrict__ W,
                         const float* __restrict__ b,
                         float4* __restrict__ out,
                         int n_tok) {
    extern __shared__ float4 sWall[];              // NWARP * PAD_F4 float4
    __shared__ float s_tok[NWARP][MAXTOK];         // warp-private token strips

    const int tid  = threadIdx.x;
    const int lane = tid & 31;
    const int w    = tid >> 5;
    const int bid  = blockIdx.x;
    const int*  pi  = (const int*)ntok_raw;
    const int2* pi2 = (const int2*)ntok_raw;

    // ---- balanced contiguous token partition ----
    const int grid  = gridDim.x;
    const int q     = n_tok / grid;
    const int rem   = n_tok - q * grid;
    const int base  = q * bid + min(bid, rem);
    const int count = q + (bid < rem ? 1 : 0);     // <= 56

    // ---- issue ALL global loads up front (latency overlapped) ----
    // W slice: 12 coalesced float4 per lane
    const float4* Wg = (const float4*)W + w * WF4;
    float4 wv[12];
#pragma unroll
    for (int r = 0; r < 12; r++)
        wv[r] = __ldg(Wg + lane + 32 * r);

    // tokens under both dtype interpretations (2 per lane cover count<=64)
    int a32_0 = 0, a64_0 = 0, a32_1 = 0, a64_1 = 0;
    if (lane < count) {
        int idx = base + lane;
        a32_0 = pi[idx];
        a64_0 = pi2[idx].x;
    }
    if (32 + lane < count) {
        int idx = base + 32 + lane;
        a32_1 = pi[idx];
        a64_1 = pi2[idx].x;
    }

    // bias for channels [w*128 + lane*4 .. +3]
    const float4 bias = __ldg((const float4*)b + (w * 32 + lane));

    // dtype probe (head of buffer, L2-broadcast)
    int probe = (lane < 16) ? pi[2 * lane + 1] : 0;
    unsigned any = __ballot_sync(0xFFFFFFFFu, probe != 0);
    const bool is64 = (any == 0);

    // ---- stage tokens into this warp's private strip ----
    if (lane < count)
        s_tok[w][lane] = (float)(is64 ? a64_0 : a32_0);
    if (32 + lane < count)
        s_tok[w][32 + lane] = (float)(is64 ? a64_1 : a32_1);

    // ---- stage W slice into padded SMEM (write addr k -> k + k/12) ----
    float4* sw = sWall + w * PAD_F4;
#pragma unroll
    for (int r = 0; r < 12; r++) {
        int k = lane + 32 * r;
        sw[k + k / 12] = wv[r];
    }
    __syncwarp();

    // ---- per-lane coefficients from SMEM (stride-13, conflict-free) ----
    const float4* myW = sw + lane * 13;
    float A[4], B[4], C[4];
#pragma unroll
    for (int c4 = 0; c4 < 4; c4++) {
        float4 f0 = myW[3 * c4 + 0];               // w0 w1 w2 w3
        float4 f1 = myW[3 * c4 + 1];               // w4 w5 w6 w7
        float4 f2 = myW[3 * c4 + 2];               // w8 w9 w10 w11
        A[c4] = f0.x + f0.w + f1.z + f2.y;
        B[c4] = f0.y + f0.z + 2.0f * (f1.x + f2.x + f2.z);
        C[c4] = f0.z + 2.0f * f1.x - f1.y + f2.x + f2.z;
    }
    C[0] += bias.x; C[1] += bias.y; C[2] += bias.z; C[3] += bias.w;

    // ---- streaming loop: LDS-broadcast token + 2 FMAs/ch + STG.128 ----
    const int row_f4 = D_MODEL / 4;                // 256 float4 per token row
    float4* outp = out + (size_t)base * row_f4 + (w * 32 + lane);
    const float* tok = s_tok[w];

#pragma unroll 4
    for (int k = 0; k < count; k++) {
        float t = tok[k];                          // all lanes same addr: free
        float4 o;
        o.x = fmaf(fmaf(A[0], t, B[0]), t, C[0]);
        o.y = fmaf(fmaf(A[1], t, B[1]), t, C[1]);
        o.z = fmaf(fmaf(A[2], t, B[2]), t, C[2]);
        o.w = fmaf(fmaf(A[3], t, B[3]), t, C[3]);
        __stcs(outp, o);                           // evict-first: never re-read
        outp += row_f4;
    }
}

extern "C" void kernel_launch(void* const* d_in, const int* in_sizes, int n_in,
                              void* d_out, int out_size) {
    const void*  ntok = d_in[0];                 // int64 or int32 tokens [B*S]
    const float* W    = (const float*)d_in[1];   // [D_MODEL, 12] row-major
    const float* b    = (const float*)d_in[2];   // [D_MODEL]
    float4* out = (float4*)d_out;

    int n_tok = in_sizes[0];                     // 32768

    cudaFuncSetAttribute(n2_embed_v13_kernel,
                         cudaFuncAttributeMaxDynamicSharedMemorySize,
                         SMEM_BYTES);
    n2_embed_v13_kernel<<<GRID, TPB, SMEM_BYTES>>>(ntok, W, b, out, n_tok);
}